// round 7
// baseline (speedup 1.0000x reference)
#include <cuda_runtime.h>
#include <cuda_fp16.h>
#include <math.h>

#define Nn 8
#define Cc 256
#define Ll 512
#define Kk 100
#define ROWS (Nn * Ll)          // 4096
#define INV_TEMP 2.0f           // 1/0.5
#define EPS 1e-8f

// Scratch (no runtime allocation allowed)
__device__ __half g_zh[ROWS * Cc];     // z transposed + normalized, fp16 (2MB)
__device__ __half g_ch[ROWS * Cc];     // c transposed + normalized * INV_TEMP

// ---------------------------------------------------------------------------
// Fully fused pre-pass: norms + transpose + normalize + fp16 convert.
// grid=256: [which(2)][n(8)][ltile32(16)], block=256.
// Stage a 32(l) x 256(c) fp32 slab in shared (accumulating sum-of-squares
// during the load), compute the 32 row norms, emit normalized fp16 rows.
// Block 0 thread 0 zeroes out[0].
// ---------------------------------------------------------------------------
__global__ void prep_k(const float* __restrict__ z, const float* __restrict__ c,
                       float* __restrict__ out)
{
    __shared__ float slab[Cc][33];      // [c][l], pad 33
    __shared__ float part[8][33];
    __shared__ float inv_sh[32];

    int bb    = blockIdx.x;
    int lt    = bb & 15;
    int n     = (bb >> 4) & 7;
    int which = bb >> 7;

    if (bb == 0 && threadIdx.x == 0) out[0] = 0.0f;

    int cols = which ? (Ll + 1) : Ll;
    const float* src = (which ? c : z) + (size_t)n * Cc * cols + (which ? 1 : 0)
                     + lt * 32;

    int tx = threadIdx.x & 31;          // l lane
    int ty = threadIdx.x >> 5;          // c group (32 c's each)

    float acc = 0.f;
#pragma unroll 8
    for (int i = 0; i < 32; i++) {
        int cc = ty * 32 + i;
        float v = src[(size_t)cc * cols + tx];
        slab[cc][tx] = v;
        acc += v * v;
    }
    part[ty][tx] = acc;
    __syncthreads();

    if (threadIdx.x < 32) {
        float s = 0.f;
#pragma unroll
        for (int k = 0; k < 8; k++) s += part[k][tx];
        float iv = 1.0f / fmaxf(sqrtf(s), EPS);
        if (which) iv *= INV_TEMP;
        inv_sh[tx] = iv;
    }
    __syncthreads();

    // Write phase: 16 threads per row, each emits 16 halves (2x uint4).
    int ch   = threadIdx.x & 15;
    int lrow = threadIdx.x >> 4;        // 0..15
    __half* gout = which ? g_ch : g_zh;
#pragma unroll
    for (int p = 0; p < 2; p++) {
        int l = p * 16 + lrow;
        float iv = inv_sh[l];
        int row = n * Ll + lt * 32 + l;
        __half hh[16];
#pragma unroll
        for (int k = 0; k < 16; k++)
            hh[k] = __float2half_rn(slab[16 * ch + k][l] * iv);
        uint4* dst = (uint4*)(gout + (size_t)row * Cc) + 2 * ch;
        dst[0] = *(uint4*)&hh[0];
        dst[1] = *(uint4*)&hh[8];
    }
}

// ---------------------------------------------------------------------------
// Main: one block per row, 128 threads = 8 half-warps. Half-warp h owns dots
// d = h + 8*it (13 iters; d==100 is the positive). Rows pre-normalized fp16:
// the dot IS the logit. Per lane: 2 coalesced LDG.128 + 8 HFMA2 + 4 shuffles.
// ---------------------------------------------------------------------------
__global__ void logits_k(const int* __restrict__ neg_inds, float* __restrict__ out)
{
    __shared__ uint4 c_sh[32];
    __shared__ float logit_sh[Kk + 1];

    int row = blockIdx.x;
    int tid = threadIdx.x;
    int h   = tid >> 4;
    int hl  = tid & 15;
    unsigned hmask = 0xFFFFu << (tid & 16);

    if (tid < 32)
        c_sh[tid] = ((const uint4*)(g_ch + (size_t)row * Cc))[tid];
    __syncthreads();

    uint4 ca = c_sh[hl];
    uint4 cb = c_sh[16 + hl];
    __half2 cc0 = *(__half2*)&ca.x, cc1 = *(__half2*)&ca.y;
    __half2 cc2 = *(__half2*)&ca.z, cc3 = *(__half2*)&ca.w;
    __half2 cc4 = *(__half2*)&cb.x, cc5 = *(__half2*)&cb.y;
    __half2 cc6 = *(__half2*)&cb.z, cc7 = *(__half2*)&cb.w;

    const int* inds = neg_inds + (size_t)row * Kk;

#pragma unroll 1
    for (int it = 0; it < 13; it++) {
        int d = h + it * 8;
        if (d <= Kk) {
            int j = (d == Kk) ? row : __ldg(&inds[d]);
            const uint4* zr = (const uint4*)(g_zh + (size_t)j * Cc);
            uint4 za = zr[hl];
            uint4 zb = zr[16 + hl];

            __half2 a0 = __float2half2_rn(0.f);
            __half2 a1 = __float2half2_rn(0.f);
            a0 = __hfma2(*(__half2*)&za.x, cc0, a0);
            a0 = __hfma2(*(__half2*)&za.y, cc1, a0);
            a0 = __hfma2(*(__half2*)&za.z, cc2, a0);
            a0 = __hfma2(*(__half2*)&za.w, cc3, a0);
            a1 = __hfma2(*(__half2*)&zb.x, cc4, a1);
            a1 = __hfma2(*(__half2*)&zb.y, cc5, a1);
            a1 = __hfma2(*(__half2*)&zb.z, cc6, a1);
            a1 = __hfma2(*(__half2*)&zb.w, cc7, a1);

            float2 f0 = __half22float2(a0);
            float2 f1 = __half22float2(a1);
            float s = (f0.x + f0.y) + (f1.x + f1.y);
#pragma unroll
            for (int off = 8; off; off >>= 1)
                s += __shfl_xor_sync(hmask, s, off);
            if (hl == 0)
                logit_sh[(d == Kk) ? 0 : d + 1] = s;
        }
    }
    __syncthreads();

    if (tid < 32) {
        int lane = tid;
        float v0 = logit_sh[lane];
        float v1 = (lane + 32 < Kk + 1) ? logit_sh[lane + 32] : -INFINITY;
        float v2 = (lane + 64 < Kk + 1) ? logit_sh[lane + 64] : -INFINITY;
        float v3 = (lane + 96 < Kk + 1) ? logit_sh[lane + 96] : -INFINITY;
        float m = fmaxf(fmaxf(v0, v1), fmaxf(v2, v3));
#pragma unroll
        for (int off = 16; off; off >>= 1)
            m = fmaxf(m, __shfl_xor_sync(0xffffffffu, m, off));
        float e = __expf(v0 - m)
                + ((lane + 32 < Kk + 1) ? __expf(v1 - m) : 0.0f)
                + ((lane + 64 < Kk + 1) ? __expf(v2 - m) : 0.0f)
                + ((lane + 96 < Kk + 1) ? __expf(v3 - m) : 0.0f);
#pragma unroll
        for (int off = 16; off; off >>= 1)
            e += __shfl_xor_sync(0xffffffffu, e, off);
        if (lane == 0) {
            float item = m + logf(e) - logit_sh[0];
            atomicAdd(out, item * (1.0f / (float)ROWS));
        }
    }
}

extern "C" void kernel_launch(void* const* d_in, const int* in_sizes, int n_in,
                              void* d_out, int out_size)
{
    const float* z  = (const float*)d_in[0];   // (8, 256, 512)
    const float* c  = (const float*)d_in[1];   // (8, 256, 513)
    const int* inds = (const int*)d_in[2];     // (8, 512, 100)
    float* out = (float*)d_out;

    prep_k<<<256, 256>>>(z, c, out);
    logits_k<<<ROWS, 128>>>(inds, out);
}

// round 8
// speedup vs baseline: 1.1238x; 1.1238x over previous
#include <cuda_runtime.h>
#include <cuda_fp16.h>
#include <cuda_fp8.h>
#include <math.h>

#define Nn 8
#define Cc 256
#define Ll 512
#define Kk 100
#define ROWS (Nn * Ll)          // 4096
#define INV_TEMP 2.0f           // 1/0.5
#define EPS 1e-8f

// Scratch (no runtime allocation allowed)
__device__ unsigned char g_z8[ROWS * Cc];  // z transposed + normalized, e5m2 (1MB)
__device__ __half g_ch[ROWS * Cc];         // c transposed + normalized * INV_TEMP

// ---------------------------------------------------------------------------
// Fused pre-pass: norms + transpose + normalize + quantize.
// grid=256: [which(2)][n(8)][ltile32(16)], block=256 (tx = l lane, ty = c grp).
// Load phase: stage 256c x 32l fp32 slab, accumulate sum-of-squares inline.
// Write phase (conflict-free): lane tx reads slab[32*ch+tx][l] -> bank tx+l.
// z -> e5m2 bytes (exact fp16-truncation format), c -> fp16 with INV_TEMP.
// ---------------------------------------------------------------------------
__global__ void prep_k(const float* __restrict__ z, const float* __restrict__ c,
                       float* __restrict__ out)
{
    __shared__ float slab[Cc][33];
    __shared__ float part[8][33];
    __shared__ float inv_sh[32];

    int bb    = blockIdx.x;
    int lt    = bb & 15;
    int n     = (bb >> 4) & 7;
    int which = bb >> 7;

    if (bb == 0 && threadIdx.x == 0) out[0] = 0.0f;

    int cols = which ? (Ll + 1) : Ll;
    const float* src = (which ? c : z) + (size_t)n * Cc * cols + (which ? 1 : 0)
                     + lt * 32;

    int tx = threadIdx.x & 31;          // l lane
    int ty = threadIdx.x >> 5;          // c group

    float acc = 0.f;
#pragma unroll 8
    for (int i = 0; i < 32; i++) {
        int cc = ty * 32 + i;
        float v = src[(size_t)cc * cols + tx];
        slab[cc][tx] = v;
        acc += v * v;
    }
    part[ty][tx] = acc;
    __syncthreads();

    if (threadIdx.x < 32) {
        float s = 0.f;
#pragma unroll
        for (int k = 0; k < 8; k++) s += part[k][tx];
        float iv = 1.0f / fmaxf(sqrtf(s), EPS);
        if (which) iv *= INV_TEMP;
        inv_sh[tx] = iv;
    }
    __syncthreads();

    // Write phase: ty covers 4 l's; lanes sweep c contiguously.
#pragma unroll
    for (int i = 0; i < 4; i++) {
        int l   = ty * 4 + i;
        float iv = inv_sh[l];
        int row = n * Ll + lt * 32 + l;
        if (which == 0) {
            unsigned char* dst = g_z8 + (size_t)row * Cc;
#pragma unroll
            for (int ch = 0; ch < 8; ch++) {
                int c0 = ch * 32 + tx;
                float v = slab[c0][l] * iv;
                dst[c0] = (unsigned char)__nv_cvt_float_to_fp8(v, __NV_SATFINITE, __NV_E5M2);
            }
        } else {
            __half* dst = g_ch + (size_t)row * Cc;
#pragma unroll
            for (int ch = 0; ch < 8; ch++) {
                int c0 = ch * 32 + tx;
                dst[c0] = __float2half_rn(slab[c0][l] * iv);
            }
        }
    }
}

// ---------------------------------------------------------------------------
// Main: one block per row, 128 threads = 8 half-warps. Half-warp h owns dots
// d = h + 8*it (13 iters; d==100 is the positive). z rows are 256 B of e5m2:
// ONE LDG.128 per half-warp per dot. Decode = PRMT byte-shift (e5m2<<8 IS
// fp16), then 8 HFMA2. 4 shuffles per dot; the dot IS the logit.
// ---------------------------------------------------------------------------
__global__ void logits_k(const int* __restrict__ neg_inds, float* __restrict__ out)
{
    __shared__ uint4 c_sh[32];
    __shared__ float logit_sh[Kk + 1];

    int row = blockIdx.x;
    int tid = threadIdx.x;
    int h   = tid >> 4;
    int hl  = tid & 15;
    unsigned hmask = 0xFFFFu << (tid & 16);

    if (tid < 32)
        c_sh[tid] = ((const uint4*)(g_ch + (size_t)row * Cc))[tid];
    __syncthreads();

    // lane's 16 consecutive c elements [16*hl, 16*hl+16) as 8 half2
    uint4 ca = c_sh[2 * hl];
    uint4 cb = c_sh[2 * hl + 1];
    __half2 cc0 = *(__half2*)&ca.x, cc1 = *(__half2*)&ca.y;
    __half2 cc2 = *(__half2*)&ca.z, cc3 = *(__half2*)&ca.w;
    __half2 cc4 = *(__half2*)&cb.x, cc5 = *(__half2*)&cb.y;
    __half2 cc6 = *(__half2*)&cb.z, cc7 = *(__half2*)&cb.w;

    const int* inds = neg_inds + (size_t)row * Kk;

#pragma unroll 1
    for (int it = 0; it < 13; it++) {
        int d = h + it * 8;
        if (d <= Kk) {
            int j = (d == Kk) ? row : __ldg(&inds[d]);
            // 16 e5m2 elems [16*hl, 16*hl+16) in one 16B load
            uint4 zp = ((const uint4*)(g_z8 + (size_t)j * Cc))[hl];

            __half2 a0 = __float2half2_rn(0.f);
            __half2 a1 = __float2half2_rn(0.f);
#define STEP2(u, clo, chi, acc) do {                                          \
            unsigned _lo, _hi;                                                \
            asm("prmt.b32 %0, %1, %2, 0x1404;" : "=r"(_lo) : "r"(u), "r"(0)); \
            asm("prmt.b32 %0, %1, %2, 0x3424;" : "=r"(_hi) : "r"(u), "r"(0)); \
            acc = __hfma2(*(__half2*)&_lo, clo, acc);                         \
            acc = __hfma2(*(__half2*)&_hi, chi, acc);                         \
        } while (0)
            STEP2(zp.x, cc0, cc1, a0);
            STEP2(zp.y, cc2, cc3, a1);
            STEP2(zp.z, cc4, cc5, a0);
            STEP2(zp.w, cc6, cc7, a1);
#undef STEP2
            float2 f0 = __half22float2(a0);
            float2 f1 = __half22float2(a1);
            float s = (f0.x + f0.y) + (f1.x + f1.y);
#pragma unroll
            for (int off = 8; off; off >>= 1)
                s += __shfl_xor_sync(hmask, s, off);
            if (hl == 0)
                logit_sh[(d == Kk) ? 0 : d + 1] = s;
        }
    }
    __syncthreads();

    if (tid < 32) {
        int lane = tid;
        float v0 = logit_sh[lane];
        float v1 = (lane + 32 < Kk + 1) ? logit_sh[lane + 32] : -INFINITY;
        float v2 = (lane + 64 < Kk + 1) ? logit_sh[lane + 64] : -INFINITY;
        float v3 = (lane + 96 < Kk + 1) ? logit_sh[lane + 96] : -INFINITY;
        float m = fmaxf(fmaxf(v0, v1), fmaxf(v2, v3));
#pragma unroll
        for (int off = 16; off; off >>= 1)
            m = fmaxf(m, __shfl_xor_sync(0xffffffffu, m, off));
        float e = __expf(v0 - m)
                + ((lane + 32 < Kk + 1) ? __expf(v1 - m) : 0.0f)
                + ((lane + 64 < Kk + 1) ? __expf(v2 - m) : 0.0f)
                + ((lane + 96 < Kk + 1) ? __expf(v3 - m) : 0.0f);
#pragma unroll
        for (int off = 16; off; off >>= 1)
            e += __shfl_xor_sync(0xffffffffu, e, off);
        if (lane == 0) {
            float item = m + logf(e) - logit_sh[0];
            atomicAdd(out, item * (1.0f / (float)ROWS));
        }
    }
}

extern "C" void kernel_launch(void* const* d_in, const int* in_sizes, int n_in,
                              void* d_out, int out_size)
{
    const float* z  = (const float*)d_in[0];   // (8, 256, 512)
    const float* c  = (const float*)d_in[1];   // (8, 256, 513)
    const int* inds = (const int*)d_in[2];     // (8, 512, 100)
    float* out = (float*)d_out;

    prep_k<<<256, 256>>>(z, c, out);
    logits_k<<<ROWS, 128>>>(inds, out);
}